// round 1
// baseline (speedup 1.0000x reference)
#include <cuda_runtime.h>
#include <math.h>

// Problem constants
#define EMB   1024
#define EXPD  2048
#define NE    8
#define NTOK  8192            // 4 * 2048
#define NPAIR (NTOK * 2)      // top-2

// ---------------- device scratch (no cudaMalloc allowed) ----------------
__device__ int   g_cnt[NE];
__device__ int   g_cnt2[NE];
__device__ int   g_off[NE];
__device__ int   g_pair_tok[NPAIR];
__device__ int   g_slot_of[NPAIR];     // [t*2+k] -> slot in expert-sorted order
__device__ float g_topk_p[NPAIR];
__device__ int   g_topk_e[NPAIR];
__device__ float g_h[(size_t)NPAIR * EXPD];     // stage1 out  (134 MB)
__device__ float g_gb[(size_t)NPAIR * EXPD];    // stage2 out  (134 MB)
__device__ float g_y[(size_t)NPAIR * EMB];      // stage3 out  ( 67 MB)

// ---------------- init ----------------
__global__ void init_kernel() {
    int i = threadIdx.x;
    if (i < NE) { g_cnt[i] = 0; g_cnt2[i] = 0; }
}

// ---------------- router: one warp per token ----------------
__global__ void router_kernel(const float* __restrict__ x,
                              const float* __restrict__ wr,
                              const float* __restrict__ br) {
    int gtid = blockIdx.x * blockDim.x + threadIdx.x;
    int t = gtid >> 5;
    int lane = gtid & 31;
    if (t >= NTOK) return;
    const float* xr = x + (size_t)t * EMB;

    float acc[NE];
#pragma unroll
    for (int e = 0; e < NE; e++) acc[e] = 0.f;
    for (int i = lane; i < EMB; i += 32) {
        float xv = xr[i];
        const float* w = wr + i * NE;
#pragma unroll
        for (int e = 0; e < NE; e++) acc[e] += xv * w[e];
    }
#pragma unroll
    for (int e = 0; e < NE; e++) {
#pragma unroll
        for (int o = 16; o > 0; o >>= 1)
            acc[e] += __shfl_xor_sync(0xffffffffu, acc[e], o);
    }
    if (lane == 0) {
        float l[NE];
        float mx = -1e30f;
#pragma unroll
        for (int e = 0; e < NE; e++) { l[e] = acc[e] + br[e]; mx = fmaxf(mx, l[e]); }
        float p[NE], s = 0.f;
#pragma unroll
        for (int e = 0; e < NE; e++) { p[e] = __expf(l[e] - mx); s += p[e]; }
        float inv = 1.0f / s;
        // top-1 (first occurrence on ties, matching lax.top_k)
        int e0 = 0;
#pragma unroll
        for (int e = 1; e < NE; e++) if (l[e] > l[e0]) e0 = e;
        // top-2
        int e1 = (e0 == 0) ? 1 : 0;
#pragma unroll
        for (int e = 0; e < NE; e++) if (e != e0 && l[e] > l[e1]) e1 = e;
        g_topk_e[2 * t + 0] = e0;
        g_topk_e[2 * t + 1] = e1;
        g_topk_p[2 * t + 0] = p[e0] * inv;
        g_topk_p[2 * t + 1] = p[e1] * inv;
        atomicAdd(&g_cnt[e0], 1);
        atomicAdd(&g_cnt[e1], 1);
    }
}

// ---------------- exclusive prefix sum over 8 counts ----------------
__global__ void scan_kernel() {
    if (threadIdx.x == 0 && blockIdx.x == 0) {
        int run = 0;
        for (int e = 0; e < NE; e++) { g_off[e] = run; run += g_cnt[e]; }
    }
}

// ---------------- bucket pairs by expert ----------------
__global__ void build_kernel() {
    int t = blockIdx.x * blockDim.x + threadIdx.x;
    if (t >= NTOK) return;
#pragma unroll
    for (int k = 0; k < 2; k++) {
        int e = g_topk_e[2 * t + k];
        int s = g_off[e] + atomicAdd(&g_cnt2[e], 1);
        g_pair_tok[s] = t;
        g_slot_of[2 * t + k] = s;
    }
}

// ---------------- grouped SGEMM: C[slot, N] = A[slot-or-token, K] @ B_e[K, N] + bias_e ----------------
// 128x128 tile, BK=8, 256 threads, 8x8 per-thread microtile.
__global__ void __launch_bounds__(256)
moe_gemm(const float* __restrict__ Asrc,   // x (gather by token) or g_h/g_gb (slot rows)
         const float* __restrict__ Ball,   // per-expert weight, row-major [K,N]
         const float* __restrict__ bias,   // per-expert bias [N]
         float* __restrict__ C,            // slot-major [slot, N]
         int Kdim, int Ndim, int gather, int relu) {
    const int e = blockIdx.z;
    const int nrows = g_cnt[e];
    const int m0loc = blockIdx.y * 128;
    if (m0loc >= nrows) return;
    const int m0 = g_off[e] + m0loc;
    const int mrows = min(128, nrows - m0loc);
    const int n0 = blockIdx.x * 128;
    const float* B = Ball + (size_t)e * Kdim * Ndim;

    __shared__ float As[8][128];
    __shared__ float Bs[8][128];

    const int tid = threadIdx.x;
    const int tx = tid & 15;          // 0..15  -> col group *8
    const int ty = tid >> 4;          // 0..15  -> row group *8

    // A load mapping: 2 threads per row, float4 each
    const int arow = tid >> 1;
    const int ak = (tid & 1) * 4;
    const float* Arow = nullptr;
    if (arow < mrows) {
        int slot = m0 + arow;
        int r = gather ? g_pair_tok[slot] : slot;
        Arow = Asrc + (size_t)r * Kdim;
    }
    // B load mapping: thread -> (krow, 4 cols)
    const int brow = tid >> 5;        // 0..7
    const int bn = (tid & 31) * 4;    // 0..124

    float c[8][8];
#pragma unroll
    for (int i = 0; i < 8; i++)
#pragma unroll
        for (int j = 0; j < 8; j++) c[i][j] = 0.f;

    const int ktiles = Kdim >> 3;
    for (int kt = 0; kt < ktiles; kt++) {
        float4 av = make_float4(0.f, 0.f, 0.f, 0.f);
        if (Arow) av = *reinterpret_cast<const float4*>(Arow + kt * 8 + ak);
        As[ak + 0][arow] = av.x;
        As[ak + 1][arow] = av.y;
        As[ak + 2][arow] = av.z;
        As[ak + 3][arow] = av.w;

        float4 bv = *reinterpret_cast<const float4*>(
            B + (size_t)(kt * 8 + brow) * Ndim + n0 + bn);
        *reinterpret_cast<float4*>(&Bs[brow][bn]) = bv;

        __syncthreads();

#pragma unroll
        for (int kk = 0; kk < 8; kk++) {
            float4 a0 = *reinterpret_cast<const float4*>(&As[kk][ty * 8]);
            float4 a1 = *reinterpret_cast<const float4*>(&As[kk][ty * 8 + 4]);
            float4 b0 = *reinterpret_cast<const float4*>(&Bs[kk][tx * 8]);
            float4 b1 = *reinterpret_cast<const float4*>(&Bs[kk][tx * 8 + 4]);
            float a[8] = {a0.x, a0.y, a0.z, a0.w, a1.x, a1.y, a1.z, a1.w};
            float b[8] = {b0.x, b0.y, b0.z, b0.w, b1.x, b1.y, b1.z, b1.w};
#pragma unroll
            for (int i = 0; i < 8; i++)
#pragma unroll
                for (int j = 0; j < 8; j++) c[i][j] = fmaf(a[i], b[j], c[i][j]);
        }
        __syncthreads();
    }

    // epilogue
    const float* bset = bias + (size_t)e * Ndim + n0 + tx * 8;
#pragma unroll
    for (int i = 0; i < 8; i++) {
        int row = ty * 8 + i;
        if (row >= mrows) break;
        float* Crow = C + (size_t)(m0 + row) * Ndim + n0 + tx * 8;
#pragma unroll
        for (int j = 0; j < 8; j++) {
            float v = c[i][j] + bset[j];
            if (relu) v = fmaxf(v, 0.f);
            Crow[j] = v;
        }
    }
}

// ---------------- combine: out[t] = p0*y[s0] + p1*y[s1] ----------------
__global__ void combine_kernel(float* __restrict__ out) {
    int t = blockIdx.x;
    int d = threadIdx.x * 4;   // 256 threads * 4 = 1024
    float p0 = g_topk_p[2 * t + 0];
    float p1 = g_topk_p[2 * t + 1];
    int s0 = g_slot_of[2 * t + 0];
    int s1 = g_slot_of[2 * t + 1];
    float4 y0 = *reinterpret_cast<const float4*>(&g_y[(size_t)s0 * EMB + d]);
    float4 y1 = *reinterpret_cast<const float4*>(&g_y[(size_t)s1 * EMB + d]);
    float4 o;
    o.x = p0 * y0.x + p1 * y1.x;
    o.y = p0 * y0.y + p1 * y1.y;
    o.z = p0 * y0.z + p1 * y1.z;
    o.w = p0 * y0.w + p1 * y1.w;
    *reinterpret_cast<float4*>(&out[(size_t)t * EMB + d]) = o;
}

// ---------------- launch ----------------
extern "C" void kernel_launch(void* const* d_in, const int* in_sizes, int n_in,
                              void* d_out, int out_size) {
    const float* x  = (const float*)d_in[0];
    const float* wr = (const float*)d_in[1];
    const float* br = (const float*)d_in[2];
    const float* w1 = (const float*)d_in[3];
    const float* b1 = (const float*)d_in[4];
    const float* wg = (const float*)d_in[5];
    const float* bg = (const float*)d_in[6];
    const float* w2 = (const float*)d_in[7];
    const float* b2 = (const float*)d_in[8];
    float* out = (float*)d_out;

    void *ph, *pg, *py;
    cudaGetSymbolAddress(&ph, g_h);
    cudaGetSymbolAddress(&pg, g_gb);
    cudaGetSymbolAddress(&py, g_y);
    float* h = (float*)ph;
    float* g = (float*)pg;
    float* y = (float*)py;

    init_kernel<<<1, 32>>>();
    router_kernel<<<(NTOK * 32) / 256, 256>>>(x, wr, br);
    scan_kernel<<<1, 32>>>();
    build_kernel<<<NTOK / 256, 256>>>();

    // stage 1: h = gather(x) @ w1[e] + b1[e]          K=1024 N=2048
    moe_gemm<<<dim3(EXPD / 128, 128, NE), 256>>>(x, w1, b1, h, EMB, EXPD, 1, 0);
    // stage 2: g = relu(h @ wg[e] + bg[e])            K=2048 N=2048
    moe_gemm<<<dim3(EXPD / 128, 128, NE), 256>>>(h, wg, bg, g, EXPD, EXPD, 0, 1);
    // stage 3: y = g @ w2[e] + b2[e]                  K=2048 N=1024
    moe_gemm<<<dim3(EMB / 128, 128, NE), 256>>>(g, w2, b2, y, EXPD, EMB, 0, 0);

    combine_kernel<<<NTOK, 256>>>(out);
}

// round 3
// speedup vs baseline: 2.2358x; 2.2358x over previous
#include <cuda_runtime.h>
#include <cuda_bf16.h>
#include <stdint.h>
#include <math.h>

#define EMB   1024
#define EXPD  2048
#define NE    8
#define NTOK  8192
#define NPAIR (NTOK*2)

// GEMM tiling
#define BM 128
#define BN 128
#define BK 32
#define PADK 40                       // bf16 elems per smem row (80 B, conflict-free)
#define ROWB (PADK*2)                 // 80 bytes
#define TILE_B (BM*ROWB)              // 10240 B per tile
#define BUF_B (4*TILE_B)              // Ahi,Alo,Bhi,Blo
#define GEMM_SMEM (2*BUF_B)           // 81920 B double buffered

// ================= device scratch (no cudaMalloc allowed) =================
__device__ int   g_cnt[NE];
__device__ int   g_cnt2[NE];
__device__ int   g_off[NE];
__device__ int   g_pair_tok[NPAIR];
__device__ int   g_slot_of[NPAIR];
__device__ float g_topk_p[NPAIR];
__device__ int   g_topk_e[NPAIR];

__device__ __nv_bfloat16 g_xhi[(size_t)NTOK*EMB];
__device__ __nv_bfloat16 g_xlo[(size_t)NTOK*EMB];
__device__ __nv_bfloat16 g_w1hi[(size_t)NE*EXPD*EMB];   // [e][n][k]
__device__ __nv_bfloat16 g_w1lo[(size_t)NE*EXPD*EMB];
__device__ __nv_bfloat16 g_wghi[(size_t)NE*EXPD*EXPD];
__device__ __nv_bfloat16 g_wglo[(size_t)NE*EXPD*EXPD];
__device__ __nv_bfloat16 g_w2hi[(size_t)NE*EMB*EXPD];
__device__ __nv_bfloat16 g_w2lo[(size_t)NE*EMB*EXPD];
__device__ __nv_bfloat16 g_hhi[(size_t)NPAIR*EXPD];
__device__ __nv_bfloat16 g_hlo[(size_t)NPAIR*EXPD];
__device__ __nv_bfloat16 g_ghi[(size_t)NPAIR*EXPD];
__device__ __nv_bfloat16 g_glo[(size_t)NPAIR*EXPD];
__device__ float g_y[(size_t)NPAIR*EMB];

// ================= helpers =================
__device__ __forceinline__ uint32_t smem_u32(const void* p) {
    uint32_t a;
    asm("{ .reg .u64 t; cvta.to.shared.u64 t, %1; cvt.u32.u64 %0, t; }" : "=r"(a) : "l"(p));
    return a;
}

#define CP_ASYNC16(dst, src, sz) \
    asm volatile("cp.async.cg.shared.global [%0], [%1], 16, %2;" :: "r"(dst), "l"(src), "r"(sz))
#define CP_COMMIT() asm volatile("cp.async.commit_group;")
#define CP_WAIT0()  asm volatile("cp.async.wait_group 0;")

#define LDSM4(r, addr) \
    asm volatile("ldmatrix.sync.aligned.m8n8.x4.shared.b16 {%0,%1,%2,%3}, [%4];" \
        : "=r"((r)[0]), "=r"((r)[1]), "=r"((r)[2]), "=r"((r)[3]) : "r"(addr))

#define MMA16816(d, a, b0, b1) \
    asm volatile("mma.sync.aligned.m16n8k16.row.col.f32.bf16.bf16.f32 " \
        "{%0,%1,%2,%3},{%4,%5,%6,%7},{%8,%9},{%0,%1,%2,%3};" \
        : "+f"((d)[0]), "+f"((d)[1]), "+f"((d)[2]), "+f"((d)[3]) \
        : "r"((a)[0]), "r"((a)[1]), "r"((a)[2]), "r"((a)[3]), "r"(b0), "r"(b1))

// ================= small kernels =================
__global__ void init_kernel() {
    int i = threadIdx.x;
    if (i < NE) { g_cnt[i] = 0; g_cnt2[i] = 0; }
}

__global__ void router_kernel(const float* __restrict__ x,
                              const float* __restrict__ wr,
                              const float* __restrict__ br) {
    int gtid = blockIdx.x * blockDim.x + threadIdx.x;
    int t = gtid >> 5;
    int lane = gtid & 31;
    if (t >= NTOK) return;
    const float* xr = x + (size_t)t * EMB;
    float acc[NE];
#pragma unroll
    for (int e = 0; e < NE; e++) acc[e] = 0.f;
    for (int i = lane; i < EMB; i += 32) {
        float xv = xr[i];
        const float* w = wr + i * NE;
#pragma unroll
        for (int e = 0; e < NE; e++) acc[e] += xv * w[e];
    }
#pragma unroll
    for (int e = 0; e < NE; e++) {
#pragma unroll
        for (int o = 16; o > 0; o >>= 1)
            acc[e] += __shfl_xor_sync(0xffffffffu, acc[e], o);
    }
    if (lane == 0) {
        float l[NE];
        float mx = -1e30f;
#pragma unroll
        for (int e = 0; e < NE; e++) { l[e] = acc[e] + br[e]; mx = fmaxf(mx, l[e]); }
        float p[NE], s = 0.f;
#pragma unroll
        for (int e = 0; e < NE; e++) { p[e] = __expf(l[e] - mx); s += p[e]; }
        float inv = 1.0f / s;
        int e0 = 0;
#pragma unroll
        for (int e = 1; e < NE; e++) if (l[e] > l[e0]) e0 = e;
        int e1 = (e0 == 0) ? 1 : 0;
#pragma unroll
        for (int e = 0; e < NE; e++) if (e != e0 && l[e] > l[e1]) e1 = e;
        g_topk_e[2 * t + 0] = e0;
        g_topk_e[2 * t + 1] = e1;
        g_topk_p[2 * t + 0] = p[e0] * inv;
        g_topk_p[2 * t + 1] = p[e1] * inv;
        atomicAdd(&g_cnt[e0], 1);
        atomicAdd(&g_cnt[e1], 1);
    }
}

__global__ void scan_kernel() {
    if (threadIdx.x == 0 && blockIdx.x == 0) {
        int run = 0;
        for (int e = 0; e < NE; e++) { g_off[e] = run; run += g_cnt[e]; }
    }
}

__global__ void build_kernel() {
    int t = blockIdx.x * blockDim.x + threadIdx.x;
    if (t >= NTOK) return;
#pragma unroll
    for (int k = 0; k < 2; k++) {
        int e = g_topk_e[2 * t + k];
        int s = g_off[e] + atomicAdd(&g_cnt2[e], 1);
        g_pair_tok[s] = t;
        g_slot_of[2 * t + k] = s;
    }
}

__global__ void convert_x(const float* __restrict__ x) {
    size_t i = ((size_t)blockIdx.x * blockDim.x + threadIdx.x) * 4;
    if (i >= (size_t)NTOK * EMB) return;
    float4 v = *(const float4*)(x + i);
    __nv_bfloat16 h0 = __float2bfloat16(v.x), h1 = __float2bfloat16(v.y);
    __nv_bfloat16 h2 = __float2bfloat16(v.z), h3 = __float2bfloat16(v.w);
    *(__nv_bfloat162*)(g_xhi + i)     = __halves2bfloat162(h0, h1);
    *(__nv_bfloat162*)(g_xhi + i + 2) = __halves2bfloat162(h2, h3);
    __nv_bfloat16 l0 = __float2bfloat16(v.x - __bfloat162float(h0));
    __nv_bfloat16 l1 = __float2bfloat16(v.y - __bfloat162float(h1));
    __nv_bfloat16 l2 = __float2bfloat16(v.z - __bfloat162float(h2));
    __nv_bfloat16 l3 = __float2bfloat16(v.w - __bfloat162float(h3));
    *(__nv_bfloat162*)(g_xlo + i)     = __halves2bfloat162(l0, l1);
    *(__nv_bfloat162*)(g_xlo + i + 2) = __halves2bfloat162(l2, l3);
}

__global__ void transpose_split(const float* __restrict__ W,
                                __nv_bfloat16* __restrict__ Th,
                                __nv_bfloat16* __restrict__ Tl,
                                int K, int N) {
    __shared__ float tile[32][33];
    int e = blockIdx.z;
    const float* Wb = W + (size_t)e * K * N;
    int n0 = blockIdx.x * 32, k0 = blockIdx.y * 32;
    int tx = threadIdx.x, ty = threadIdx.y;
#pragma unroll
    for (int i = 0; i < 32; i += 8)
        tile[ty + i][tx] = Wb[(size_t)(k0 + ty + i) * N + n0 + tx];
    __syncthreads();
    __nv_bfloat16* Thb = Th + (size_t)e * K * N;
    __nv_bfloat16* Tlb = Tl + (size_t)e * K * N;
#pragma unroll
    for (int i = 0; i < 32; i += 8) {
        float v = tile[tx][ty + i];
        __nv_bfloat16 h = __float2bfloat16(v);
        float lo = v - __bfloat162float(h);
        size_t o = (size_t)(n0 + ty + i) * K + k0 + tx;
        Thb[o] = h;
        Tlb[o] = __float2bfloat16(lo);
    }
}

// ================= grouped GEMM via mma.sync (HMMA) =================
// C[slot, n0:n0+128] = sum_k A[row,k] * B[e][n][k] + bias; split-bf16 3-pass.
__global__ void __launch_bounds__(256, 1)
moe_gemm_mma(const __nv_bfloat16* __restrict__ Ahi, const __nv_bfloat16* __restrict__ Alo, int gather,
             const __nv_bfloat16* __restrict__ Bhi, const __nv_bfloat16* __restrict__ Blo,
             const float* __restrict__ bias, int Kdim, int Ndim, int relu, int mode_fp32,
             __nv_bfloat16* __restrict__ Ohi, __nv_bfloat16* __restrict__ Olo, float* __restrict__ Of) {
    extern __shared__ char smem[];
    const int e = blockIdx.z;
    const int nrows = g_cnt[e];
    const int m0loc = blockIdx.y * BM;
    if (m0loc >= nrows) return;
    const int m0 = g_off[e] + m0loc;
    const int mrows = min(BM, nrows - m0loc);
    const int n0 = blockIdx.x * BN;
    const int tid = threadIdx.x;
    const uint32_t sb = smem_u32(smem);

    // ---- load task: thread -> (row, two 16B chunks) ----
    const int lrow = tid >> 1;          // 0..127
    const int lch  = (tid & 1) * 2;     // chunk base (16B units): 0 or 2
    const __nv_bfloat16 *gAh, *gAl;
    uint32_t asz = 0;
    if (lrow < mrows) {
        int src = gather ? g_pair_tok[m0 + lrow] : (m0 + lrow);
        gAh = Ahi + (size_t)src * Kdim;
        gAl = Alo + (size_t)src * Kdim;
        asz = 16;
    } else { gAh = Ahi; gAl = Alo; }
    const size_t Boff = (size_t)e * Kdim * Ndim + (size_t)(n0 + lrow) * Kdim;
    const __nv_bfloat16* gBh = Bhi + Boff;
    const __nv_bfloat16* gBl = Blo + Boff;
    const uint32_t drow = (uint32_t)lrow * ROWB + (uint32_t)lch * 16;

    // ---- mma identity ----
    const int lane = tid & 31, wid = tid >> 5;
    const int warpM = wid & 1;          // 2 warps along M (64 rows each)
    const int warpN = wid >> 1;         // 4 warps along N (32 cols each)
    // lane part of ldmatrix address: row=(lane&15), col8=(lane>>4)
    const uint32_t lm_off = (uint32_t)(lane & 15) * ROWB + (uint32_t)(lane >> 4) * 16;

    float c[4][4][4];
#pragma unroll
    for (int i = 0; i < 4; i++)
#pragma unroll
        for (int j = 0; j < 4; j++)
#pragma unroll
            for (int q = 0; q < 4; q++) c[i][j][q] = 0.f;

    const int NC = Kdim / BK;

    // prologue: fill buffer 0
    {
        const int ko = lch * 8;
        uint32_t d0 = sb + drow;
        CP_ASYNC16(d0,              gAh + ko,     asz);
        CP_ASYNC16(d0 + 16,         gAh + ko + 8, asz);
        CP_ASYNC16(d0 + TILE_B,     gAl + ko,     asz);
        CP_ASYNC16(d0 + TILE_B + 16,gAl + ko + 8, asz);
        CP_ASYNC16(d0 + 2*TILE_B,     gBh + ko,     16u);
        CP_ASYNC16(d0 + 2*TILE_B + 16,gBh + ko + 8, 16u);
        CP_ASYNC16(d0 + 3*TILE_B,     gBl + ko,     16u);
        CP_ASYNC16(d0 + 3*TILE_B + 16,gBl + ko + 8, 16u);
        CP_COMMIT();
    }

    for (int cc = 0; cc < NC; cc++) {
        CP_WAIT0();
        __syncthreads();
        const int buf = cc & 1;
        if (cc + 1 < NC) {
            const int ko = (cc + 1) * BK + lch * 8;
            uint32_t d0 = sb + (buf ^ 1) * BUF_B + drow;
            CP_ASYNC16(d0,              gAh + ko,     asz);
            CP_ASYNC16(d0 + 16,         gAh + ko + 8, asz);
            CP_ASYNC16(d0 + TILE_B,     gAl + ko,     asz);
            CP_ASYNC16(d0 + TILE_B + 16,gAl + ko + 8, asz);
            CP_ASYNC16(d0 + 2*TILE_B,     gBh + ko,     16u);
            CP_ASYNC16(d0 + 2*TILE_B + 16,gBh + ko + 8, 16u);
            CP_ASYNC16(d0 + 3*TILE_B,     gBl + ko,     16u);
            CP_ASYNC16(d0 + 3*TILE_B + 16,gBl + ko + 8, 16u);
            CP_COMMIT();
        }
        const uint32_t sAh = sb + buf * BUF_B;
        const uint32_t sAl = sAh + TILE_B;
        const uint32_t sBh = sAh + 2 * TILE_B;
        const uint32_t sBl = sAh + 3 * TILE_B;

#pragma unroll
        for (int ks = 0; ks < 2; ks++) {
            uint32_t ah[4][4], al[4][4], bh[2][4], bl[2][4];
            const uint32_t kso = (uint32_t)ks * 32;
#pragma unroll
            for (int mi = 0; mi < 4; mi++) {
                uint32_t ra = (uint32_t)(warpM * 64 + mi * 16) * ROWB + kso + lm_off;
                LDSM4(ah[mi], sAh + ra);
                LDSM4(al[mi], sAl + ra);
            }
#pragma unroll
            for (int ng = 0; ng < 2; ng++) {
                uint32_t rb = (uint32_t)(warpN * 32 + ng * 16) * ROWB + kso + lm_off;
                LDSM4(bh[ng], sBh + rb);
                LDSM4(bl[ng], sBl + rb);
            }
#pragma unroll
            for (int mi = 0; mi < 4; mi++)
#pragma unroll
                for (int ng = 0; ng < 2; ng++)
#pragma unroll
                    for (int j = 0; j < 2; j++) {
                        int ni = ng * 2 + j;
                        MMA16816(c[mi][ni], ah[mi], bh[ng][j], bh[ng][j + 2]);
                        MMA16816(c[mi][ni], ah[mi], bl[ng][j], bl[ng][j + 2]);
                        MMA16816(c[mi][ni], al[mi], bh[ng][j], bh[ng][j + 2]);
                    }
        }
    }

    // ---- epilogue ----
    const float* be = bias + (size_t)e * Ndim;
#pragma unroll
    for (int mi = 0; mi < 4; mi++) {
        int r0 = warpM * 64 + mi * 16 + (lane >> 2);
        int r1 = r0 + 8;
#pragma unroll
        for (int ni = 0; ni < 4; ni++) {
            int cg = n0 + warpN * 32 + ni * 8 + (lane & 3) * 2;
            float2 bb = *(const float2*)(be + cg);
            float v00 = c[mi][ni][0] + bb.x, v01 = c[mi][ni][1] + bb.y;
            float v10 = c[mi][ni][2] + bb.x, v11 = c[mi][ni][3] + bb.y;
            if (relu) {
                v00 = fmaxf(v00, 0.f); v01 = fmaxf(v01, 0.f);
                v10 = fmaxf(v10, 0.f); v11 = fmaxf(v11, 0.f);
            }
            if (mode_fp32) {
                if (r0 < mrows) *(float2*)(Of + (size_t)(m0 + r0) * Ndim + cg) = make_float2(v00, v01);
                if (r1 < mrows) *(float2*)(Of + (size_t)(m0 + r1) * Ndim + cg) = make_float2(v10, v11);
            } else {
                if (r0 < mrows) {
                    size_t o = (size_t)(m0 + r0) * Ndim + cg;
                    __nv_bfloat16 h0 = __float2bfloat16(v00), h1 = __float2bfloat16(v01);
                    *(__nv_bfloat162*)(Ohi + o) = __halves2bfloat162(h0, h1);
                    *(__nv_bfloat162*)(Olo + o) = __halves2bfloat162(
                        __float2bfloat16(v00 - __bfloat162float(h0)),
                        __float2bfloat16(v01 - __bfloat162float(h1)));
                }
                if (r1 < mrows) {
                    size_t o = (size_t)(m0 + r1) * Ndim + cg;
                    __nv_bfloat16 h0 = __float2bfloat16(v10), h1 = __float2bfloat16(v11);
                    *(__nv_bfloat162*)(Ohi + o) = __halves2bfloat162(h0, h1);
                    *(__nv_bfloat162*)(Olo + o) = __halves2bfloat162(
                        __float2bfloat16(v10 - __bfloat162float(h0)),
                        __float2bfloat16(v11 - __bfloat162float(h1)));
                }
            }
        }
    }
}

// ================= combine =================
__global__ void combine_kernel(float* __restrict__ out) {
    int t = blockIdx.x;
    int d = threadIdx.x * 4;
    float p0 = g_topk_p[2 * t + 0];
    float p1 = g_topk_p[2 * t + 1];
    int s0 = g_slot_of[2 * t + 0];
    int s1 = g_slot_of[2 * t + 1];
    float4 y0 = *reinterpret_cast<const float4*>(&g_y[(size_t)s0 * EMB + d]);
    float4 y1 = *reinterpret_cast<const float4*>(&g_y[(size_t)s1 * EMB + d]);
    float4 o;
    o.x = p0 * y0.x + p1 * y1.x;
    o.y = p0 * y0.y + p1 * y1.y;
    o.z = p0 * y0.z + p1 * y1.z;
    o.w = p0 * y0.w + p1 * y1.w;
    *reinterpret_cast<float4*>(&out[(size_t)t * EMB + d]) = o;
}

// ================= launch =================
extern "C" void kernel_launch(void* const* d_in, const int* in_sizes, int n_in,
                              void* d_out, int out_size) {
    const float* x  = (const float*)d_in[0];
    const float* wr = (const float*)d_in[1];
    const float* br = (const float*)d_in[2];
    const float* w1 = (const float*)d_in[3];
    const float* b1 = (const float*)d_in[4];
    const float* wg = (const float*)d_in[5];
    const float* bg = (const float*)d_in[6];
    const float* w2 = (const float*)d_in[7];
    const float* b2 = (const float*)d_in[8];
    float* out = (float*)d_out;

    cudaFuncSetAttribute(moe_gemm_mma, cudaFuncAttributeMaxDynamicSharedMemorySize, GEMM_SMEM);

    void* p;
    __nv_bfloat16 *xhi, *xlo, *w1hi, *w1lo, *wghi, *wglo, *w2hi, *w2lo, *hhi, *hlo, *ghi, *glo;
    float* y;
    cudaGetSymbolAddress(&p, g_xhi);  xhi  = (__nv_bfloat16*)p;
    cudaGetSymbolAddress(&p, g_xlo);  xlo  = (__nv_bfloat16*)p;
    cudaGetSymbolAddress(&p, g_w1hi); w1hi = (__nv_bfloat16*)p;
    cudaGetSymbolAddress(&p, g_w1lo); w1lo = (__nv_bfloat16*)p;
    cudaGetSymbolAddress(&p, g_wghi); wghi = (__nv_bfloat16*)p;
    cudaGetSymbolAddress(&p, g_wglo); wglo = (__nv_bfloat16*)p;
    cudaGetSymbolAddress(&p, g_w2hi); w2hi = (__nv_bfloat16*)p;
    cudaGetSymbolAddress(&p, g_w2lo); w2lo = (__nv_bfloat16*)p;
    cudaGetSymbolAddress(&p, g_hhi);  hhi  = (__nv_bfloat16*)p;
    cudaGetSymbolAddress(&p, g_hlo);  hlo  = (__nv_bfloat16*)p;
    cudaGetSymbolAddress(&p, g_ghi);  ghi  = (__nv_bfloat16*)p;
    cudaGetSymbolAddress(&p, g_glo);  glo  = (__nv_bfloat16*)p;
    cudaGetSymbolAddress(&p, g_y);    y    = (float*)p;

    init_kernel<<<1, 32>>>();

    convert_x<<<(NTOK * EMB / 4 + 255) / 256, 256>>>(x);
    transpose_split<<<dim3(EXPD / 32, EMB / 32, NE),  dim3(32, 8)>>>(w1, w1hi, w1lo, EMB,  EXPD);
    transpose_split<<<dim3(EXPD / 32, EXPD / 32, NE), dim3(32, 8)>>>(wg, wghi, wglo, EXPD, EXPD);
    transpose_split<<<dim3(EMB / 32, EXPD / 32, NE),  dim3(32, 8)>>>(w2, w2hi, w2lo, EXPD, EMB);

    router_kernel<<<(NTOK * 32) / 256, 256>>>(x, wr, br);
    scan_kernel<<<1, 32>>>();
    build_kernel<<<NTOK / 256, 256>>>();

    // stage 1: h = gather(x) @ w1[e]   K=1024 N=2048
    moe_gemm_mma<<<dim3(EXPD / BN, NPAIR / BM, NE), 256, GEMM_SMEM>>>(
        xhi, xlo, 1, w1hi, w1lo, b1, EMB, EXPD, 0, 0, hhi, hlo, nullptr);
    // stage 2: g = relu(h @ wg[e])     K=2048 N=2048
    moe_gemm_mma<<<dim3(EXPD / BN, NPAIR / BM, NE), 256, GEMM_SMEM>>>(
        hhi, hlo, 0, wghi, wglo, bg, EXPD, EXPD, 1, 0, ghi, glo, nullptr);
    // stage 3: y = g @ w2[e]           K=2048 N=1024 (fp32 out)
    moe_gemm_mma<<<dim3(EMB / BN, NPAIR / BM, NE), 256, GEMM_SMEM>>>(
        ghi, glo, 0, w2hi, w2lo, b2, EXPD, EMB, 0, 1, nullptr, nullptr, y);

    combine_kernel<<<NTOK, 256>>>(out);
}

// round 4
// speedup vs baseline: 2.2521x; 1.0073x over previous
#include <cuda_runtime.h>
#include <cuda_bf16.h>
#include <stdint.h>
#include <math.h>

#define EMB   1024
#define EXPD  2048
#define NE    8
#define NTOK  8192
#define NPAIR (NTOK*2)

// GEMM tiling
#define BM 128
#define BN 256
#define BK 32
#define PADK 40                        // bf16 elems per smem row (80 B)
#define ROWB (PADK*2)                  // 80 bytes
#define A_T (BM*ROWB)                  // 10240
#define B_T (BN*ROWB)                  // 20480
#define BUF_B (2*A_T + 2*B_T)          // Ahi,Alo,Bhi,Blo = 61440
#define GEMM_SMEM (2*BUF_B)            // 122880 double buffered

// ================= device scratch =================
__device__ int   g_cnt[NE];
__device__ int   g_cnt2[NE];
__device__ int   g_off[NE];
__device__ int   g_pair_tok[NPAIR];
__device__ int   g_slot_of[NPAIR];
__device__ float g_topk_p[NPAIR];
__device__ int   g_topk_e[NPAIR];

__device__ __nv_bfloat16 g_xhi[(size_t)NTOK*EMB];
__device__ __nv_bfloat16 g_xlo[(size_t)NTOK*EMB];
__device__ __nv_bfloat16 g_w1hi[(size_t)NE*EXPD*EMB];   // [e][n][k]
__device__ __nv_bfloat16 g_w1lo[(size_t)NE*EXPD*EMB];
__device__ __nv_bfloat16 g_wghi[(size_t)NE*EXPD*EXPD];
__device__ __nv_bfloat16 g_wglo[(size_t)NE*EXPD*EXPD];
__device__ __nv_bfloat16 g_w2hi[(size_t)NE*EMB*EXPD];
__device__ __nv_bfloat16 g_w2lo[(size_t)NE*EMB*EXPD];
__device__ __nv_bfloat16 g_hhi[(size_t)NPAIR*EXPD];
__device__ __nv_bfloat16 g_hlo[(size_t)NPAIR*EXPD];
__device__ __nv_bfloat16 g_ghi[(size_t)NPAIR*EXPD];
__device__ __nv_bfloat16 g_glo[(size_t)NPAIR*EXPD];
__device__ float g_y[(size_t)NPAIR*EMB];

// ================= helpers =================
__device__ __forceinline__ uint32_t smem_u32(const void* p) {
    uint32_t a;
    asm("{ .reg .u64 t; cvta.to.shared.u64 t, %1; cvt.u32.u64 %0, t; }" : "=r"(a) : "l"(p));
    return a;
}

#define CP_ASYNC16(dst, src, sz) \
    asm volatile("cp.async.cg.shared.global [%0], [%1], 16, %2;" :: "r"(dst), "l"(src), "r"(sz))
#define CP_COMMIT() asm volatile("cp.async.commit_group;")
#define CP_WAIT0()  asm volatile("cp.async.wait_group 0;")

#define LDSM4(r, addr) \
    asm volatile("ldmatrix.sync.aligned.m8n8.x4.shared.b16 {%0,%1,%2,%3}, [%4];" \
        : "=r"((r)[0]), "=r"((r)[1]), "=r"((r)[2]), "=r"((r)[3]) : "r"(addr))

#define MMA16816(d, a, b0, b1) \
    asm volatile("mma.sync.aligned.m16n8k16.row.col.f32.bf16.bf16.f32 " \
        "{%0,%1,%2,%3},{%4,%5,%6,%7},{%8,%9},{%0,%1,%2,%3};" \
        : "+f"((d)[0]), "+f"((d)[1]), "+f"((d)[2]), "+f"((d)[3]) \
        : "r"((a)[0]), "r"((a)[1]), "r"((a)[2]), "r"((a)[3]), "r"(b0), "r"(b1))

// ================= small kernels =================
__global__ void init_kernel() {
    int i = threadIdx.x;
    if (i < NE) { g_cnt[i] = 0; g_cnt2[i] = 0; }
}

__global__ void router_kernel(const float* __restrict__ x,
                              const float* __restrict__ wr,
                              const float* __restrict__ br) {
    int gtid = blockIdx.x * blockDim.x + threadIdx.x;
    int t = gtid >> 5;
    int lane = gtid & 31;
    if (t >= NTOK) return;
    const float* xr = x + (size_t)t * EMB;
    float acc[NE];
#pragma unroll
    for (int e = 0; e < NE; e++) acc[e] = 0.f;
    for (int i = lane; i < EMB; i += 32) {
        float xv = xr[i];
        const float* w = wr + i * NE;
#pragma unroll
        for (int e = 0; e < NE; e++) acc[e] += xv * w[e];
    }
#pragma unroll
    for (int e = 0; e < NE; e++) {
#pragma unroll
        for (int o = 16; o > 0; o >>= 1)
            acc[e] += __shfl_xor_sync(0xffffffffu, acc[e], o);
    }
    if (lane == 0) {
        float l[NE];
        float mx = -1e30f;
#pragma unroll
        for (int e = 0; e < NE; e++) { l[e] = acc[e] + br[e]; mx = fmaxf(mx, l[e]); }
        float p[NE], s = 0.f;
#pragma unroll
        for (int e = 0; e < NE; e++) { p[e] = __expf(l[e] - mx); s += p[e]; }
        float inv = 1.0f / s;
        int e0 = 0;
#pragma unroll
        for (int e = 1; e < NE; e++) if (l[e] > l[e0]) e0 = e;
        int e1 = (e0 == 0) ? 1 : 0;
#pragma unroll
        for (int e = 0; e < NE; e++) if (e != e0 && l[e] > l[e1]) e1 = e;
        g_topk_e[2 * t + 0] = e0;
        g_topk_e[2 * t + 1] = e1;
        g_topk_p[2 * t + 0] = p[e0] * inv;
        g_topk_p[2 * t + 1] = p[e1] * inv;
        atomicAdd(&g_cnt[e0], 1);
        atomicAdd(&g_cnt[e1], 1);
    }
}

__global__ void scan_kernel() {
    if (threadIdx.x == 0 && blockIdx.x == 0) {
        int run = 0;
        for (int e = 0; e < NE; e++) { g_off[e] = run; run += g_cnt[e]; }
    }
}

__global__ void build_kernel() {
    int t = blockIdx.x * blockDim.x + threadIdx.x;
    if (t >= NTOK) return;
#pragma unroll
    for (int k = 0; k < 2; k++) {
        int e = g_topk_e[2 * t + k];
        int s = g_off[e] + atomicAdd(&g_cnt2[e], 1);
        g_pair_tok[s] = t;
        g_slot_of[2 * t + k] = s;
    }
}

__global__ void convert_x(const float* __restrict__ x) {
    size_t i = ((size_t)blockIdx.x * blockDim.x + threadIdx.x) * 4;
    if (i >= (size_t)NTOK * EMB) return;
    float4 v = *(const float4*)(x + i);
    __nv_bfloat16 h0 = __float2bfloat16(v.x), h1 = __float2bfloat16(v.y);
    __nv_bfloat16 h2 = __float2bfloat16(v.z), h3 = __float2bfloat16(v.w);
    *(__nv_bfloat162*)(g_xhi + i)     = __halves2bfloat162(h0, h1);
    *(__nv_bfloat162*)(g_xhi + i + 2) = __halves2bfloat162(h2, h3);
    __nv_bfloat16 l0 = __float2bfloat16(v.x - __bfloat162float(h0));
    __nv_bfloat16 l1 = __float2bfloat16(v.y - __bfloat162float(h1));
    __nv_bfloat16 l2 = __float2bfloat16(v.z - __bfloat162float(h2));
    __nv_bfloat16 l3 = __float2bfloat16(v.w - __bfloat162float(h3));
    *(__nv_bfloat162*)(g_xlo + i)     = __halves2bfloat162(l0, l1);
    *(__nv_bfloat162*)(g_xlo + i + 2) = __halves2bfloat162(l2, l3);
}

__global__ void transpose_split(const float* __restrict__ W,
                                __nv_bfloat16* __restrict__ Th,
                                __nv_bfloat16* __restrict__ Tl,
                                int K, int N) {
    __shared__ float tile[32][33];
    int e = blockIdx.z;
    const float* Wb = W + (size_t)e * K * N;
    int n0 = blockIdx.x * 32, k0 = blockIdx.y * 32;
    int tx = threadIdx.x, ty = threadIdx.y;
#pragma unroll
    for (int i = 0; i < 32; i += 8)
        tile[ty + i][tx] = Wb[(size_t)(k0 + ty + i) * N + n0 + tx];
    __syncthreads();
    __nv_bfloat16* Thb = Th + (size_t)e * K * N;
    __nv_bfloat16* Tlb = Tl + (size_t)e * K * N;
#pragma unroll
    for (int i = 0; i < 32; i += 8) {
        float v = tile[tx][ty + i];
        __nv_bfloat16 h = __float2bfloat16(v);
        float lo = v - __bfloat162float(h);
        size_t o = (size_t)(n0 + ty + i) * K + k0 + tx;
        Thb[o] = h;
        Tlb[o] = __float2bfloat16(lo);
    }
}

// ================= grouped GEMM via mma.sync (HMMA), 128x256 tile =================
__global__ void __launch_bounds__(256, 1)
moe_gemm_mma(const __nv_bfloat16* __restrict__ Ahi, const __nv_bfloat16* __restrict__ Alo, int gather,
             const __nv_bfloat16* __restrict__ Bhi, const __nv_bfloat16* __restrict__ Blo,
             const float* __restrict__ bias, int Kdim, int Ndim, int relu, int mode_fp32,
             __nv_bfloat16* __restrict__ Ohi, __nv_bfloat16* __restrict__ Olo, float* __restrict__ Of) {
    extern __shared__ char smem[];
    const int e = blockIdx.z;
    const int nrows = g_cnt[e];
    const int m0loc = blockIdx.y * BM;
    if (m0loc >= nrows) return;
    const int m0 = g_off[e] + m0loc;
    const int mrows = min(BM, nrows - m0loc);
    const int n0 = blockIdx.x * BN;
    const int tid = threadIdx.x;
    const uint32_t sb = smem_u32(smem);

    // ---- load task ----
    // thread -> q = tid/4 (0..63), ch = tid%4 (16B chunk within 64B of K-chunk data)
    const int q  = tid >> 2;
    const int ch = tid & 3;
    // A rows handled: q and q+64 (both hi and lo)
    const __nv_bfloat16 *gA0h, *gA0l, *gA1h, *gA1l;
    uint32_t asz0 = 0, asz1 = 0;
    {
        int r0 = q, r1 = q + 64;
        int s0 = (r0 < mrows) ? (gather ? g_pair_tok[m0 + r0] : (m0 + r0)) : 0;
        int s1 = (r1 < mrows) ? (gather ? g_pair_tok[m0 + r1] : (m0 + r1)) : 0;
        asz0 = (r0 < mrows) ? 16u : 0u;
        asz1 = (r1 < mrows) ? 16u : 0u;
        gA0h = Ahi + (size_t)s0 * Kdim; gA0l = Alo + (size_t)s0 * Kdim;
        gA1h = Ahi + (size_t)s1 * Kdim; gA1l = Alo + (size_t)s1 * Kdim;
    }
    // B rows handled: q + 64*p, p=0..3 (hi and lo)
    const size_t Bbase = (size_t)e * Kdim * Ndim;
    const __nv_bfloat16* gBh[4];
    const __nv_bfloat16* gBl[4];
#pragma unroll
    for (int p2 = 0; p2 < 4; p2++) {
        size_t o = Bbase + (size_t)(n0 + q + 64 * p2) * Kdim;
        gBh[p2] = Bhi + o;
        gBl[p2] = Blo + o;
    }
    const uint32_t chB = (uint32_t)ch * 16;

    // ---- mma identity ----
    const int lane = tid & 31, wid = tid >> 5;
    const int warpM = wid & 1;          // 2 warps along M (64 rows)
    const int warpN = wid >> 1;         // 4 warps along N (64 cols)
    const uint32_t lm_off = (uint32_t)(lane & 15) * ROWB + (uint32_t)(lane >> 4) * 16;

    float c[4][8][4];
#pragma unroll
    for (int i = 0; i < 4; i++)
#pragma unroll
        for (int j = 0; j < 8; j++)
#pragma unroll
            for (int qq = 0; qq < 4; qq++) c[i][j][qq] = 0.f;

    const int NC = Kdim / BK;

    // prefetch helper (macro to keep pointers in regs)
#define PREFETCH(bufbase, ko)                                                      \
    {                                                                              \
        uint32_t dA0 = (bufbase) + (uint32_t)q * ROWB + chB;                       \
        uint32_t dA1 = dA0 + 64u * ROWB;                                           \
        CP_ASYNC16(dA0,        gA0h + (ko), asz0);                                 \
        CP_ASYNC16(dA1,        gA1h + (ko), asz1);                                 \
        CP_ASYNC16(dA0 + A_T,  gA0l + (ko), asz0);                                 \
        CP_ASYNC16(dA1 + A_T,  gA1l + (ko), asz1);                                 \
        uint32_t dB = (bufbase) + 2u * A_T + (uint32_t)q * ROWB + chB;             \
        _Pragma("unroll")                                                          \
        for (int p2 = 0; p2 < 4; p2++) {                                           \
            CP_ASYNC16(dB + (uint32_t)(64 * p2) * ROWB,       gBh[p2] + (ko), 16u);\
            CP_ASYNC16(dB + (uint32_t)(64 * p2) * ROWB + B_T, gBl[p2] + (ko), 16u);\
        }                                                                          \
        CP_COMMIT();                                                               \
    }

    PREFETCH(sb, ch * 8);

    for (int cc = 0; cc < NC; cc++) {
        CP_WAIT0();
        __syncthreads();
        const int buf = cc & 1;
        if (cc + 1 < NC) {
            PREFETCH(sb + (uint32_t)(buf ^ 1) * BUF_B, (cc + 1) * BK + ch * 8);
        }
        const uint32_t sAh = sb + (uint32_t)buf * BUF_B;
        const uint32_t sAl = sAh + A_T;
        const uint32_t sBh = sAh + 2 * A_T;
        const uint32_t sBl = sBh + B_T;

#pragma unroll
        for (int ks = 0; ks < 2; ks++) {
            uint32_t ah[4][4], al[4][4], bh[4][4], bl[4][4];
            const uint32_t kso = (uint32_t)ks * 32;
#pragma unroll
            for (int mi = 0; mi < 4; mi++) {
                uint32_t ra = (uint32_t)(warpM * 64 + mi * 16) * ROWB + kso + lm_off;
                LDSM4(ah[mi], sAh + ra);
                LDSM4(al[mi], sAl + ra);
            }
#pragma unroll
            for (int ng = 0; ng < 4; ng++) {
                uint32_t rb = (uint32_t)(warpN * 64 + ng * 16) * ROWB + kso + lm_off;
                LDSM4(bh[ng], sBh + rb);
                LDSM4(bl[ng], sBl + rb);
            }
#pragma unroll
            for (int mi = 0; mi < 4; mi++)
#pragma unroll
                for (int ng = 0; ng < 4; ng++)
#pragma unroll
                    for (int j = 0; j < 2; j++) {
                        int ni = ng * 2 + j;
                        MMA16816(c[mi][ni], ah[mi], bh[ng][j], bh[ng][j + 2]);
                        MMA16816(c[mi][ni], ah[mi], bl[ng][j], bl[ng][j + 2]);
                        MMA16816(c[mi][ni], al[mi], bh[ng][j], bh[ng][j + 2]);
                    }
        }
        __syncthreads();
    }

    // ---- epilogue ----
    const float* be = bias + (size_t)e * Ndim;
#pragma unroll
    for (int mi = 0; mi < 4; mi++) {
        int r0 = warpM * 64 + mi * 16 + (lane >> 2);
        int r1 = r0 + 8;
#pragma unroll
        for (int ni = 0; ni < 8; ni++) {
            int cg = n0 + warpN * 64 + ni * 8 + (lane & 3) * 2;
            float2 bb = *(const float2*)(be + cg);
            float v00 = c[mi][ni][0] + bb.x, v01 = c[mi][ni][1] + bb.y;
            float v10 = c[mi][ni][2] + bb.x, v11 = c[mi][ni][3] + bb.y;
            if (relu) {
                v00 = fmaxf(v00, 0.f); v01 = fmaxf(v01, 0.f);
                v10 = fmaxf(v10, 0.f); v11 = fmaxf(v11, 0.f);
            }
            if (mode_fp32) {
                if (r0 < mrows) *(float2*)(Of + (size_t)(m0 + r0) * Ndim + cg) = make_float2(v00, v01);
                if (r1 < mrows) *(float2*)(Of + (size_t)(m0 + r1) * Ndim + cg) = make_float2(v10, v11);
            } else {
                if (r0 < mrows) {
                    size_t o = (size_t)(m0 + r0) * Ndim + cg;
                    __nv_bfloat16 h0 = __float2bfloat16(v00), h1 = __float2bfloat16(v01);
                    *(__nv_bfloat162*)(Ohi + o) = __halves2bfloat162(h0, h1);
                    *(__nv_bfloat162*)(Olo + o) = __halves2bfloat162(
                        __float2bfloat16(v00 - __bfloat162float(h0)),
                        __float2bfloat16(v01 - __bfloat162float(h1)));
                }
                if (r1 < mrows) {
                    size_t o = (size_t)(m0 + r1) * Ndim + cg;
                    __nv_bfloat16 h0 = __float2bfloat16(v10), h1 = __float2bfloat16(v11);
                    *(__nv_bfloat162*)(Ohi + o) = __halves2bfloat162(h0, h1);
                    *(__nv_bfloat162*)(Olo + o) = __halves2bfloat162(
                        __float2bfloat16(v10 - __bfloat162float(h0)),
                        __float2bfloat16(v11 - __bfloat162float(h1)));
                }
            }
        }
    }
#undef PREFETCH
}

// ================= combine =================
__global__ void combine_kernel(float* __restrict__ out) {
    int t = blockIdx.x;
    int d = threadIdx.x * 4;
    float p0 = g_topk_p[2 * t + 0];
    float p1 = g_topk_p[2 * t + 1];
    int s0 = g_slot_of[2 * t + 0];
    int s1 = g_slot_of[2 * t + 1];
    float4 y0 = *reinterpret_cast<const float4*>(&g_y[(size_t)s0 * EMB + d]);
    float4 y1 = *reinterpret_cast<const float4*>(&g_y[(size_t)s1 * EMB + d]);
    float4 o;
    o.x = p0 * y0.x + p1 * y1.x;
    o.y = p0 * y0.y + p1 * y1.y;
    o.z = p0 * y0.z + p1 * y1.z;
    o.w = p0 * y0.w + p1 * y1.w;
    *reinterpret_cast<float4*>(&out[(size_t)t * EMB + d]) = o;
}

// ================= launch =================
extern "C" void kernel_launch(void* const* d_in, const int* in_sizes, int n_in,
                              void* d_out, int out_size) {
    const float* x  = (const float*)d_in[0];
    const float* wr = (const float*)d_in[1];
    const float* br = (const float*)d_in[2];
    const float* w1 = (const float*)d_in[3];
    const float* b1 = (const float*)d_in[4];
    const float* wg = (const float*)d_in[5];
    const float* bg = (const float*)d_in[6];
    const float* w2 = (const float*)d_in[7];
    const float* b2 = (const float*)d_in[8];
    float* out = (float*)d_out;

    cudaFuncSetAttribute(moe_gemm_mma, cudaFuncAttributeMaxDynamicSharedMemorySize, GEMM_SMEM);

    void* p;
    __nv_bfloat16 *xhi, *xlo, *w1hi, *w1lo, *wghi, *wglo, *w2hi, *w2lo, *hhi, *hlo, *ghi, *glo;
    float* y;
    cudaGetSymbolAddress(&p, g_xhi);  xhi  = (__nv_bfloat16*)p;
    cudaGetSymbolAddress(&p, g_xlo);  xlo  = (__nv_bfloat16*)p;
    cudaGetSymbolAddress(&p, g_w1hi); w1hi = (__nv_bfloat16*)p;
    cudaGetSymbolAddress(&p, g_w1lo); w1lo = (__nv_bfloat16*)p;
    cudaGetSymbolAddress(&p, g_wghi); wghi = (__nv_bfloat16*)p;
    cudaGetSymbolAddress(&p, g_wglo); wglo = (__nv_bfloat16*)p;
    cudaGetSymbolAddress(&p, g_w2hi); w2hi = (__nv_bfloat16*)p;
    cudaGetSymbolAddress(&p, g_w2lo); w2lo = (__nv_bfloat16*)p;
    cudaGetSymbolAddress(&p, g_hhi);  hhi  = (__nv_bfloat16*)p;
    cudaGetSymbolAddress(&p, g_hlo);  hlo  = (__nv_bfloat16*)p;
    cudaGetSymbolAddress(&p, g_ghi);  ghi  = (__nv_bfloat16*)p;
    cudaGetSymbolAddress(&p, g_glo);  glo  = (__nv_bfloat16*)p;
    cudaGetSymbolAddress(&p, g_y);    y    = (float*)p;

    init_kernel<<<1, 32>>>();

    convert_x<<<(NTOK * EMB / 4 + 255) / 256, 256>>>(x);
    transpose_split<<<dim3(EXPD / 32, EMB / 32, NE),  dim3(32, 8)>>>(w1, w1hi, w1lo, EMB,  EXPD);
    transpose_split<<<dim3(EXPD / 32, EXPD / 32, NE), dim3(32, 8)>>>(wg, wghi, wglo, EXPD, EXPD);
    transpose_split<<<dim3(EMB / 32, EXPD / 32, NE),  dim3(32, 8)>>>(w2, w2hi, w2lo, EXPD, EMB);

    router_kernel<<<(NTOK * 32) / 256, 256>>>(x, wr, br);
    scan_kernel<<<1, 32>>>();
    build_kernel<<<NTOK / 256, 256>>>();

    // stage 1: h = gather(x) @ w1[e]   K=1024 N=2048
    moe_gemm_mma<<<dim3(EXPD / BN, NPAIR / BM, NE), 256, GEMM_SMEM>>>(
        xhi, xlo, 1, w1hi, w1lo, b1, EMB, EXPD, 0, 0, hhi, hlo, nullptr);
    // stage 2: g = relu(h @ wg[e])     K=2048 N=2048
    moe_gemm_mma<<<dim3(EXPD / BN, NPAIR / BM, NE), 256, GEMM_SMEM>>>(
        hhi, hlo, 0, wghi, wglo, bg, EXPD, EXPD, 1, 0, ghi, glo, nullptr);
    // stage 3: y = g @ w2[e]           K=2048 N=1024 (fp32 out)
    moe_gemm_mma<<<dim3(EMB / BN, NPAIR / BM, NE), 256, GEMM_SMEM>>>(
        ghi, glo, 0, w2hi, w2lo, b2, EXPD, EMB, 0, 1, nullptr, nullptr, y);

    combine_kernel<<<NTOK, 256>>>(out);
}

// round 6
// speedup vs baseline: 3.2864x; 1.4593x over previous
#include <cuda_runtime.h>
#include <stdint.h>
#include <math.h>

#define EMB   1024
#define EXPD  2048
#define NE    8
#define NTOK  8192
#define NPAIR (NTOK*2)

// GEMM tiling: 128x128 block, BK=64 (int8), 8 warps 2x4 -> warp 64x32
#define ROWQ 80                        // 64 data bytes + 16 pad (16B-aligned rows)
#define QT (128*ROWQ)                  // 10240 per tile
#define QBUF (4*QT)                    // A1,A2,B1,B2 = 40960
#define QSMEM (2*QBUF)                 // 81920 double buffered

// ================= device scratch =================
__device__ int   g_cnt[NE];
__device__ int   g_cnt2[NE];
__device__ int   g_off[NE];
__device__ int   g_pair_tok[NPAIR];
__device__ int   g_slot_of[NPAIR];
__device__ float g_topk_p[NPAIR];
__device__ int   g_topk_e[NPAIR];

// int8 digit arrays
__device__ int8_t g_xq1[(size_t)NTOK*EMB];
__device__ int8_t g_xq2[(size_t)NTOK*EMB];
__device__ float  g_sx[NTOK];
__device__ int8_t g_w1q1[(size_t)NE*EXPD*EMB];   // [e][n][k]
__device__ int8_t g_w1q2[(size_t)NE*EXPD*EMB];
__device__ int8_t g_wgq1[(size_t)NE*EXPD*EXPD];
__device__ int8_t g_wgq2[(size_t)NE*EXPD*EXPD];
__device__ int8_t g_w2q1[(size_t)NE*EMB*EXPD];
__device__ int8_t g_w2q2[(size_t)NE*EMB*EXPD];
__device__ unsigned g_cm1[NE*EXPD];              // colmax w1 (float-as-uint)
__device__ unsigned g_cmg[NE*EXPD];
__device__ unsigned g_cm2[NE*EMB];
__device__ float  g_sw1[NE*EXPD];
__device__ float  g_swg[NE*EXPD];
__device__ float  g_sw2[NE*EMB];
// fp32 stage outputs + digits for h, g
__device__ float  g_hf[(size_t)NPAIR*EXPD];
__device__ int8_t g_hq1[(size_t)NPAIR*EXPD];
__device__ int8_t g_hq2[(size_t)NPAIR*EXPD];
__device__ float  g_sh[NPAIR];
__device__ float  g_gf[(size_t)NPAIR*EXPD];
__device__ int8_t g_gq1[(size_t)NPAIR*EXPD];
__device__ int8_t g_gq2[(size_t)NPAIR*EXPD];
__device__ float  g_sg[NPAIR];
__device__ float  g_y[(size_t)NPAIR*EMB];

// ================= helpers =================
__device__ __forceinline__ uint32_t smem_u32(const void* p) {
    uint32_t a;
    asm("{ .reg .u64 t; cvta.to.shared.u64 t, %1; cvt.u32.u64 %0, t; }" : "=r"(a) : "l"(p));
    return a;
}

#define CP_ASYNC16(dst, src, sz) \
    asm volatile("cp.async.cg.shared.global [%0], [%1], 16, %2;" :: "r"(dst), "l"(src), "r"(sz))
#define CP_COMMIT() asm volatile("cp.async.commit_group;")
#define CP_WAIT0()  asm volatile("cp.async.wait_group 0;")

#define LDSM4(r, addr) \
    asm volatile("ldmatrix.sync.aligned.m8n8.x4.shared.b16 {%0,%1,%2,%3}, [%4];" \
        : "=r"((r)[0]), "=r"((r)[1]), "=r"((r)[2]), "=r"((r)[3]) : "r"(addr))

#define MMAS8(d, a, b0, b1) \
    asm volatile("mma.sync.aligned.m16n8k32.row.col.s32.s8.s8.s32 " \
        "{%0,%1,%2,%3},{%4,%5,%6,%7},{%8,%9},{%0,%1,%2,%3};" \
        : "+r"((d)[0]), "+r"((d)[1]), "+r"((d)[2]), "+r"((d)[3]) \
        : "r"((a)[0]), "r"((a)[1]), "r"((a)[2]), "r"((a)[3]), "r"(b0), "r"(b1))

// ================= routing kernels =================
__global__ void init_kernel() {
    int i = threadIdx.x;
    if (i < NE) { g_cnt[i] = 0; g_cnt2[i] = 0; }
}

__global__ void zero_cmax() {
    int i = blockIdx.x * blockDim.x + threadIdx.x;
    if (i < NE * EXPD) g_cm1[i] = 0;
    if (i < NE * EXPD) g_cmg[i] = 0;
    if (i < NE * EMB)  g_cm2[i] = 0;
}

__global__ void router_kernel(const float* __restrict__ x,
                              const float* __restrict__ wr,
                              const float* __restrict__ br) {
    int gtid = blockIdx.x * blockDim.x + threadIdx.x;
    int t = gtid >> 5;
    int lane = gtid & 31;
    if (t >= NTOK) return;
    const float* xr = x + (size_t)t * EMB;
    float acc[NE];
#pragma unroll
    for (int e = 0; e < NE; e++) acc[e] = 0.f;
    for (int i = lane; i < EMB; i += 32) {
        float xv = xr[i];
        const float* w = wr + i * NE;
#pragma unroll
        for (int e = 0; e < NE; e++) acc[e] += xv * w[e];
    }
#pragma unroll
    for (int e = 0; e < NE; e++) {
#pragma unroll
        for (int o = 16; o > 0; o >>= 1)
            acc[e] += __shfl_xor_sync(0xffffffffu, acc[e], o);
    }
    if (lane == 0) {
        float l[NE];
        float mx = -1e30f;
#pragma unroll
        for (int e = 0; e < NE; e++) { l[e] = acc[e] + br[e]; mx = fmaxf(mx, l[e]); }
        float p[NE], s = 0.f;
#pragma unroll
        for (int e = 0; e < NE; e++) { p[e] = __expf(l[e] - mx); s += p[e]; }
        float inv = 1.0f / s;
        int e0 = 0;
#pragma unroll
        for (int e = 1; e < NE; e++) if (l[e] > l[e0]) e0 = e;
        int e1 = (e0 == 0) ? 1 : 0;
#pragma unroll
        for (int e = 0; e < NE; e++) if (e != e0 && l[e] > l[e1]) e1 = e;
        g_topk_e[2 * t + 0] = e0;
        g_topk_e[2 * t + 1] = e1;
        g_topk_p[2 * t + 0] = p[e0] * inv;
        g_topk_p[2 * t + 1] = p[e1] * inv;
        atomicAdd(&g_cnt[e0], 1);
        atomicAdd(&g_cnt[e1], 1);
    }
}

__global__ void scan_kernel() {
    if (threadIdx.x == 0 && blockIdx.x == 0) {
        int run = 0;
        for (int e = 0; e < NE; e++) { g_off[e] = run; run += g_cnt[e]; }
    }
}

__global__ void build_kernel() {
    int t = blockIdx.x * blockDim.x + threadIdx.x;
    if (t >= NTOK) return;
#pragma unroll
    for (int k = 0; k < 2; k++) {
        int e = g_topk_e[2 * t + k];
        int s = g_off[e] + atomicAdd(&g_cnt2[e], 1);
        g_pair_tok[s] = t;
        g_slot_of[2 * t + k] = s;
    }
}

// ================= quantization =================
// per-row 2-digit int8: v ~= s*(q1 + q2/128), s = rowmax/127
__global__ void quantize_rows(const float* __restrict__ src,
                              int8_t* __restrict__ q1, int8_t* __restrict__ q2,
                              float* __restrict__ sc, int cols) {
    const int row = blockIdx.x;
    const float* r = src + (size_t)row * cols;
    const int tid = threadIdx.x;
    float m = 0.f;
    for (int i = tid * 4; i < cols; i += 1024) {
        float4 v = *(const float4*)(r + i);
        m = fmaxf(m, fmaxf(fmaxf(fabsf(v.x), fabsf(v.y)), fmaxf(fabsf(v.z), fabsf(v.w))));
    }
#pragma unroll
    for (int o = 16; o > 0; o >>= 1) m = fmaxf(m, __shfl_xor_sync(0xffffffffu, m, o));
    __shared__ float wm[8];
    __shared__ float fm;
    if ((tid & 31) == 0) wm[tid >> 5] = m;
    __syncthreads();
    if (tid == 0) {
        float t = 0.f;
#pragma unroll
        for (int w = 0; w < 8; w++) t = fmaxf(t, wm[w]);
        fm = t;
        sc[row] = t / 127.f;
    }
    __syncthreads();
    const float cm = fm;
    const float inv = (cm > 0.f) ? 127.f / cm : 0.f;
    const float s = cm / 127.f;
    for (int i = tid * 4; i < cols; i += 1024) {
        float4 v = *(const float4*)(r + i);
        float vv[4] = {v.x, v.y, v.z, v.w};
        char a1[4], a2[4];
#pragma unroll
        for (int j = 0; j < 4; j++) {
            int t1 = __float2int_rn(vv[j] * inv);
            t1 = max(-127, min(127, t1));
            float res = vv[j] - s * (float)t1;
            int t2 = __float2int_rn(res * inv * 128.f);
            t2 = max(-127, min(127, t2));
            a1[j] = (char)t1;
            a2[j] = (char)t2;
        }
        *(char4*)(q1 + (size_t)row * cols + i) = make_char4(a1[0], a1[1], a1[2], a1[3]);
        *(char4*)(q2 + (size_t)row * cols + i) = make_char4(a2[0], a2[1], a2[2], a2[3]);
    }
}

// colmax over K of W[e][K][N] -> cmax[e][n]
__global__ void colmax_kernel(const float* __restrict__ W, unsigned* __restrict__ cmax,
                              int K, int N) {
    int e = blockIdx.z;
    int n = blockIdx.x * 256 + threadIdx.x;
    int k0 = blockIdx.y * 128;
    const float* Wb = W + (size_t)e * K * N;
    float m = 0.f;
    for (int kk = 0; kk < 128; kk++)
        m = fmaxf(m, fabsf(Wb[(size_t)(k0 + kk) * N + n]));
    atomicMax(&cmax[e * N + n], __float_as_uint(m));
}

// transpose W[e][K][N] -> digits at [e][n][k], using colmax scales; also emit sB
__global__ void transpose_quant(const float* __restrict__ W,
                                const unsigned* __restrict__ cmax,
                                int8_t* __restrict__ q1, int8_t* __restrict__ q2,
                                float* __restrict__ sB, int K, int N) {
    __shared__ float tile[32][33];
    int e = blockIdx.z;
    const float* Wb = W + (size_t)e * K * N;
    int n0 = blockIdx.x * 32, k0 = blockIdx.y * 32;
    int tx = threadIdx.x, ty = threadIdx.y;
#pragma unroll
    for (int i = 0; i < 32; i += 8)
        tile[ty + i][tx] = Wb[(size_t)(k0 + ty + i) * N + n0 + tx];
    __syncthreads();
    int8_t* q1b = q1 + (size_t)e * K * N;
    int8_t* q2b = q2 + (size_t)e * K * N;
#pragma unroll
    for (int i = 0; i < 32; i += 8) {
        int n = n0 + ty + i;
        float cm = __uint_as_float(cmax[e * N + n]);
        float inv = (cm > 0.f) ? 127.f / cm : 0.f;
        float s = cm / 127.f;
        float v = tile[tx][ty + i];
        int t1 = __float2int_rn(v * inv);
        t1 = max(-127, min(127, t1));
        float res = v - s * (float)t1;
        int t2 = __float2int_rn(res * inv * 128.f);
        t2 = max(-127, min(127, t2));
        size_t o = (size_t)n * K + k0 + tx;
        q1b[o] = (int8_t)t1;
        q2b[o] = (int8_t)t2;
        if (k0 == 0 && tx == 0) sB[e * N + n] = s;
    }
}

// ================= grouped int8 GEMM (dual accumulator) =================
__global__ void __launch_bounds__(256, 1)
moe_gemm_i8(const int8_t* __restrict__ A1, const int8_t* __restrict__ A2,
            const float* __restrict__ sA, int gather,
            const int8_t* __restrict__ B1, const int8_t* __restrict__ B2,
            const float* __restrict__ sB, const float* __restrict__ bias,
            int Kdim, int Ndim, int relu, float* __restrict__ Out) {
    extern __shared__ char smem[];
    const int e = blockIdx.z;
    const int nrows = g_cnt[e];
    const int m0loc = blockIdx.y * 128;
    if (m0loc >= nrows) return;
    const int m0 = g_off[e] + m0loc;
    const int mrows = min(128, nrows - m0loc);
    const int n0 = blockIdx.x * 128;
    const int tid = threadIdx.x;
    const uint32_t sb = smem_u32(smem);

    // ---- load mapping: thread -> (row = tid/2, 32B half = (tid&1)*32) ----
    const int lrow = tid >> 1;
    const int lch = (tid & 1) * 32;
    const int8_t *gA1, *gA2;
    uint32_t asz;
    {
        int src = (lrow < mrows) ? (gather ? g_pair_tok[m0 + lrow] : (m0 + lrow)) : 0;
        asz = (lrow < mrows) ? 16u : 0u;
        gA1 = A1 + (size_t)src * Kdim;
        gA2 = A2 + (size_t)src * Kdim;
    }
    const size_t Bb = (size_t)e * Kdim * Ndim + (size_t)(n0 + lrow) * Kdim;
    const int8_t* gB1 = B1 + Bb;
    const int8_t* gB2 = B2 + Bb;
    const uint32_t drow = (uint32_t)lrow * ROWQ + (uint32_t)lch;

    // ---- mma identity: 8 warps = 2(M) x 4(N); warp tile 64x32 ----
    const int lane = tid & 31, wid = tid >> 5;
    const int warpM = wid & 1, warpN = wid >> 1;
    const uint32_t lm_off = (uint32_t)(lane & 15) * ROWQ + (uint32_t)(lane >> 4) * 16;

    int c1[4][4][4], c2[4][4][4];
#pragma unroll
    for (int i = 0; i < 4; i++)
#pragma unroll
        for (int j = 0; j < 4; j++)
#pragma unroll
            for (int q = 0; q < 4; q++) { c1[i][j][q] = 0; c2[i][j][q] = 0; }

    const int NC = Kdim >> 6;

#define QPREF(base, ko)                                                    \
    {                                                                      \
        uint32_t d = (base) + drow;                                        \
        CP_ASYNC16(d,               gA1 + (ko),      asz);                 \
        CP_ASYNC16(d + 16,          gA1 + (ko) + 16, asz);                 \
        CP_ASYNC16(d + QT,          gA2 + (ko),      asz);                 \
        CP_ASYNC16(d + QT + 16,     gA2 + (ko) + 16, asz);                 \
        CP_ASYNC16(d + 2*QT,        gB1 + (ko),      16u);                 \
        CP_ASYNC16(d + 2*QT + 16,   gB1 + (ko) + 16, 16u);                 \
        CP_ASYNC16(d + 3*QT,        gB2 + (ko),      16u);                 \
        CP_ASYNC16(d + 3*QT + 16,   gB2 + (ko) + 16, 16u);                 \
        CP_COMMIT();                                                       \
    }

    QPREF(sb, lch);

    for (int cc = 0; cc < NC; cc++) {
        CP_WAIT0();
        __syncthreads();
        const int buf = cc & 1;
        if (cc + 1 < NC) {
            QPREF(sb + (uint32_t)(buf ^ 1) * QBUF, (cc + 1) * 64 + lch);
        }
        const uint32_t sA1t = sb + (uint32_t)buf * QBUF;
        const uint32_t sA2t = sA1t + QT;
        const uint32_t sB1t = sA1t + 2 * QT;
        const uint32_t sB2t = sA1t + 3 * QT;

#pragma unroll
        for (int ks = 0; ks < 2; ks++) {
            const uint32_t kso = (uint32_t)ks * 32;
            uint32_t a1[4][4], a2[4][4], b1[2][4], b2[2][4];
#pragma unroll
            for (int mi = 0; mi < 4; mi++) {
                uint32_t ra = (uint32_t)(warpM * 64 + mi * 16) * ROWQ + kso + lm_off;
                LDSM4(a1[mi], sA1t + ra);
                LDSM4(a2[mi], sA2t + ra);
            }
#pragma unroll
            for (int ng = 0; ng < 2; ng++) {
                uint32_t rb = (uint32_t)(warpN * 32 + ng * 16) * ROWQ + kso + lm_off;
                LDSM4(b1[ng], sB1t + rb);
                LDSM4(b2[ng], sB2t + rb);
            }
#pragma unroll
            for (int mi = 0; mi < 4; mi++)
#pragma unroll
                for (int ng = 0; ng < 2; ng++)
#pragma unroll
                    for (int j = 0; j < 2; j++) {
                        int ni = ng * 2 + j;
                        MMAS8(c1[mi][ni], a1[mi], b1[ng][j], b1[ng][j + 2]);
                        MMAS8(c2[mi][ni], a1[mi], b2[ng][j], b2[ng][j + 2]);
                        MMAS8(c2[mi][ni], a2[mi], b1[ng][j], b1[ng][j + 2]);
                    }
        }
        __syncthreads();
    }
#undef QPREF

    // ---- epilogue: C = sA*sB*(c1 + c2/128) + bias ----
    const float* be = bias + (size_t)e * Ndim;
    const float* se = sB + (size_t)e * Ndim;
#pragma unroll
    for (int mi = 0; mi < 4; mi++) {
        int r0 = warpM * 64 + mi * 16 + (lane >> 2);
        int r1 = r0 + 8;
        float sa0 = 0.f, sa1 = 0.f;
        if (r0 < mrows) sa0 = sA[gather ? g_pair_tok[m0 + r0] : (m0 + r0)];
        if (r1 < mrows) sa1 = sA[gather ? g_pair_tok[m0 + r1] : (m0 + r1)];
#pragma unroll
        for (int ni = 0; ni < 4; ni++) {
            int cg = n0 + warpN * 32 + ni * 8 + (lane & 3) * 2;
            float2 bb = *(const float2*)(be + cg);
            float2 sn = *(const float2*)(se + cg);
            float f00 = (float)c1[mi][ni][0] + (float)c2[mi][ni][0] * 0.0078125f;
            float f01 = (float)c1[mi][ni][1] + (float)c2[mi][ni][1] * 0.0078125f;
            float f10 = (float)c1[mi][ni][2] + (float)c2[mi][ni][2] * 0.0078125f;
            float f11 = (float)c1[mi][ni][3] + (float)c2[mi][ni][3] * 0.0078125f;
            float v00 = sa0 * sn.x * f00 + bb.x;
            float v01 = sa0 * sn.y * f01 + bb.y;
            float v10 = sa1 * sn.x * f10 + bb.x;
            float v11 = sa1 * sn.y * f11 + bb.y;
            if (relu) {
                v00 = fmaxf(v00, 0.f); v01 = fmaxf(v01, 0.f);
                v10 = fmaxf(v10, 0.f); v11 = fmaxf(v11, 0.f);
            }
            if (r0 < mrows) *(float2*)(Out + (size_t)(m0 + r0) * Ndim + cg) = make_float2(v00, v01);
            if (r1 < mrows) *(float2*)(Out + (size_t)(m0 + r1) * Ndim + cg) = make_float2(v10, v11);
        }
    }
}

// ================= combine =================
__global__ void combine_kernel(float* __restrict__ out) {
    int t = blockIdx.x;
    int d = threadIdx.x * 4;
    float p0 = g_topk_p[2 * t + 0];
    float p1 = g_topk_p[2 * t + 1];
    int s0 = g_slot_of[2 * t + 0];
    int s1 = g_slot_of[2 * t + 1];
    float4 y0 = *reinterpret_cast<const float4*>(&g_y[(size_t)s0 * EMB + d]);
    float4 y1 = *reinterpret_cast<const float4*>(&g_y[(size_t)s1 * EMB + d]);
    float4 o;
    o.x = p0 * y0.x + p1 * y1.x;
    o.y = p0 * y0.y + p1 * y1.y;
    o.z = p0 * y0.z + p1 * y1.z;
    o.w = p0 * y0.w + p1 * y1.w;
    *reinterpret_cast<float4*>(&out[(size_t)t * EMB + d]) = o;
}

// ================= launch =================
extern "C" void kernel_launch(void* const* d_in, const int* in_sizes, int n_in,
                              void* d_out, int out_size) {
    const float* x  = (const float*)d_in[0];
    const float* wr = (const float*)d_in[1];
    const float* br = (const float*)d_in[2];
    const float* w1 = (const float*)d_in[3];
    const float* b1 = (const float*)d_in[4];
    const float* wg = (const float*)d_in[5];
    const float* bg = (const float*)d_in[6];
    const float* w2 = (const float*)d_in[7];
    const float* b2 = (const float*)d_in[8];
    float* out = (float*)d_out;

    cudaFuncSetAttribute(moe_gemm_i8, cudaFuncAttributeMaxDynamicSharedMemorySize, QSMEM);

    void* p;
    int8_t *xq1, *xq2, *w1q1, *w1q2, *wgq1, *wgq2, *w2q1, *w2q2;
    int8_t *hq1, *hq2, *gq1, *gq2;
    float *sx, *sw1, *swg, *sw2, *sh, *sg, *hf, *gf, *y;
    unsigned *cm1, *cmg, *cm2;
    cudaGetSymbolAddress(&p, g_xq1);  xq1 = (int8_t*)p;
    cudaGetSymbolAddress(&p, g_xq2);  xq2 = (int8_t*)p;
    cudaGetSymbolAddress(&p, g_sx);   sx  = (float*)p;
    cudaGetSymbolAddress(&p, g_w1q1); w1q1 = (int8_t*)p;
    cudaGetSymbolAddress(&p, g_w1q2); w1q2 = (int8_t*)p;
    cudaGetSymbolAddress(&p, g_wgq1); wgq1 = (int8_t*)p;
    cudaGetSymbolAddress(&p, g_wgq2); wgq2 = (int8_t*)p;
    cudaGetSymbolAddress(&p, g_w2q1); w2q1 = (int8_t*)p;
    cudaGetSymbolAddress(&p, g_w2q2); w2q2 = (int8_t*)p;
    cudaGetSymbolAddress(&p, g_cm1);  cm1 = (unsigned*)p;
    cudaGetSymbolAddress(&p, g_cmg);  cmg = (unsigned*)p;
    cudaGetSymbolAddress(&p, g_cm2);  cm2 = (unsigned*)p;
    cudaGetSymbolAddress(&p, g_sw1);  sw1 = (float*)p;
    cudaGetSymbolAddress(&p, g_swg);  swg = (float*)p;
    cudaGetSymbolAddress(&p, g_sw2);  sw2 = (float*)p;
    cudaGetSymbolAddress(&p, g_hf);   hf  = (float*)p;
    cudaGetSymbolAddress(&p, g_hq1);  hq1 = (int8_t*)p;
    cudaGetSymbolAddress(&p, g_hq2);  hq2 = (int8_t*)p;
    cudaGetSymbolAddress(&p, g_sh);   sh  = (float*)p;
    cudaGetSymbolAddress(&p, g_gf);   gf  = (float*)p;
    cudaGetSymbolAddress(&p, g_gq1);  gq1 = (int8_t*)p;
    cudaGetSymbolAddress(&p, g_gq2);  gq2 = (int8_t*)p;
    cudaGetSymbolAddress(&p, g_sg);   sg  = (float*)p;
    cudaGetSymbolAddress(&p, g_y);    y   = (float*)p;

    init_kernel<<<1, 32>>>();
    zero_cmax<<<(NE * EXPD + 255) / 256, 256>>>();

    // weight colmax
    colmax_kernel<<<dim3(EXPD / 256, EMB / 128, NE), 256>>>(w1, cm1, EMB, EXPD);
    colmax_kernel<<<dim3(EXPD / 256, EXPD / 128, NE), 256>>>(wg, cmg, EXPD, EXPD);
    colmax_kernel<<<dim3(EMB / 256, EXPD / 128, NE), 256>>>(w2, cm2, EXPD, EMB);
    // weight transpose + quantize
    transpose_quant<<<dim3(EXPD / 32, EMB / 32, NE),  dim3(32, 8)>>>(w1, cm1, w1q1, w1q2, sw1, EMB,  EXPD);
    transpose_quant<<<dim3(EXPD / 32, EXPD / 32, NE), dim3(32, 8)>>>(wg, cmg, wgq1, wgq2, swg, EXPD, EXPD);
    transpose_quant<<<dim3(EMB / 32, EXPD / 32, NE),  dim3(32, 8)>>>(w2, cm2, w2q1, w2q2, sw2, EXPD, EMB);

    // activations
    quantize_rows<<<NTOK, 256>>>(x, xq1, xq2, sx, EMB);

    router_kernel<<<(NTOK * 32) / 256, 256>>>(x, wr, br);
    scan_kernel<<<1, 32>>>();
    build_kernel<<<NTOK / 256, 256>>>();

    // stage 1: h = gather(x) @ w1[e] + b1     K=1024 N=2048
    moe_gemm_i8<<<dim3(EXPD / 128, NPAIR / 128, NE), 256, QSMEM>>>(
        xq1, xq2, sx, 1, w1q1, w1q2, sw1, b1, EMB, EXPD, 0, hf);
    quantize_rows<<<NPAIR, 256>>>(hf, hq1, hq2, sh, EXPD);

    // stage 2: g = relu(h @ wg[e] + bg)       K=2048 N=2048
    moe_gemm_i8<<<dim3(EXPD / 128, NPAIR / 128, NE), 256, QSMEM>>>(
        hq1, hq2, sh, 0, wgq1, wgq2, swg, bg, EXPD, EXPD, 1, gf);
    quantize_rows<<<NPAIR, 256>>>(gf, gq1, gq2, sg, EXPD);

    // stage 3: y = g @ w2[e] + b2             K=2048 N=1024
    moe_gemm_i8<<<dim3(EMB / 128, NPAIR / 128, NE), 256, QSMEM>>>(
        gq1, gq2, sg, 0, w2q1, w2q2, sw2, b2, EXPD, EMB, 0, y);

    combine_kernel<<<NTOK, 256>>>(out);
}